// round 9
// baseline (speedup 1.0000x reference)
#include <cuda_runtime.h>

// Controlled 2-qubit gate on a 2^26 fp32 statevector.
// Targets: qubits 0,1 -> bits 25,24. Control: qubit 2 -> bit 23.
//
// Key layout fact: within each 64MB t-stream (2^24 floats), the control bit
// is the TOP bit. So control-off = four contiguous 32MB regions (pure copy),
// control-on = four contiguous 32MB regions (gate math).
//
// This round: split the work between the copy engines (4 D2D memcpy nodes,
// 256MB traffic) and the SM kernel (gate half only, 256MB traffic), running
// as parallel branches of the captured graph via fork/join events. Goal:
// CE+SM combined request streams push DRAM utilization past the ~81.5%
// ceiling observed with SM-only traffic.

#define STREAM_ELEMS (1 << 24)          // floats per t-stream
#define HALF_ELEMS   (1 << 23)          // control half per stream
#define GQ           (HALF_ELEMS / 4)   // float4 granules in gate half per stream (2^21)

__global__ void __launch_bounds__(256) gate_half_kernel(
    const float4* __restrict__ in4,     // pre-offset to control-on region
    const float*  __restrict__ m,
    float4*       __restrict__ out4)    // pre-offset likewise
{
    const int tid = blockIdx.x * blockDim.x + threadIdx.x;  // 0 .. 2^21-1
    const int SQ = STREAM_ELEMS / 4;    // granule stride between t-streams

    float4 a0 = in4[tid];
    float4 a1 = in4[tid + SQ];
    float4 a2 = in4[tid + 2 * SQ];
    float4 a3 = in4[tid + 3 * SQ];

    const float m00 = __ldg(m + 0),  m01 = __ldg(m + 1),  m02 = __ldg(m + 2),  m03 = __ldg(m + 3);
    const float m10 = __ldg(m + 4),  m11 = __ldg(m + 5),  m12 = __ldg(m + 6),  m13 = __ldg(m + 7);
    const float m20 = __ldg(m + 8),  m21 = __ldg(m + 9),  m22 = __ldg(m + 10), m23 = __ldg(m + 11);
    const float m30 = __ldg(m + 12), m31 = __ldg(m + 13), m32 = __ldg(m + 14), m33 = __ldg(m + 15);

    float4 y0, y1, y2, y3;
    #define APPLY(c) \
        y0.c = m00 * a0.c + m01 * a1.c + m02 * a2.c + m03 * a3.c; \
        y1.c = m10 * a0.c + m11 * a1.c + m12 * a2.c + m13 * a3.c; \
        y2.c = m20 * a0.c + m21 * a1.c + m22 * a2.c + m23 * a3.c; \
        y3.c = m30 * a0.c + m31 * a1.c + m32 * a2.c + m33 * a3.c;
    APPLY(x); APPLY(y); APPLY(z); APPLY(w);
    #undef APPLY

    __stcs(out4 + tid,          y0);
    __stcs(out4 + tid + SQ,     y1);
    __stcs(out4 + tid + 2 * SQ, y2);
    __stcs(out4 + tid + 3 * SQ, y3);
}

extern "C" void kernel_launch(void* const* d_in, const int* in_sizes, int n_in,
                              void* d_out, int out_size)
{
    const float* x = (const float*)d_in[0];   // 2^26 floats
    const float* m = (const float*)d_in[1];   // 16 floats (4x4 row-major)
    float* out = (float*)d_out;               // 2^26 floats

    // One-time host-side resources (no device memory allocation; per-call
    // work below is identical and deterministic).
    static cudaStream_t s2 = nullptr;
    static cudaEvent_t ev_fork = nullptr, ev_join = nullptr;
    if (s2 == nullptr) {
        cudaStreamCreateWithFlags(&s2, cudaStreamNonBlocking);
        cudaEventCreateWithFlags(&ev_fork, cudaEventDisableTiming);
        cudaEventCreateWithFlags(&ev_join, cudaEventDisableTiming);
    }

    // Fork: copy branch on s2 (copy engines), gate branch on the main stream.
    cudaEventRecord(ev_fork, 0);
    cudaStreamWaitEvent(s2, ev_fork, 0);

    // Control-off halves: pure contiguous copies, one per t-stream.
    for (int t = 0; t < 4; t++) {
        const size_t off = (size_t)t * STREAM_ELEMS;
        cudaMemcpyAsync(out + off, x + off, (size_t)HALF_ELEMS * sizeof(float),
                        cudaMemcpyDeviceToDevice, s2);
    }
    cudaEventRecord(ev_join, s2);

    // Control-on halves: gate math, branch-free.
    const float4* in_gate  = (const float4*)(x   + HALF_ELEMS);
    float4*       out_gate = (float4*)      (out + HALF_ELEMS);
    gate_half_kernel<<<GQ / 256, 256>>>(in_gate, m, out_gate);

    // Join.
    cudaStreamWaitEvent(0, ev_join, 0);
}

// round 10
// speedup vs baseline: 1.0733x; 1.0733x over previous
#include <cuda_runtime.h>

// Controlled 2-qubit gate on a 2^26 fp32 statevector. FINAL (R4 config).
// Targets: qubits 0,1 -> bits 25,24 of the flat index. Control: qubit 2 -> bit 23.
// Structure: 1 float4 granule x 4 t-streams per thread (4 coalesced streams
// 64MB apart), warp-uniform control branch (bit 21 of granule index, uniform
// over 2^21 consecutive threads), default-cache loads, evict-first stores.
//
// Roofline: 512 MiB minimum traffic (256 read + 256 write) at the measured
// ~6.5 TB/s mixed read/write HBM3e ceiling -> ~74.5 us kernel. Verified
// bandwidth-bound across 8 structural variants (MLP 4/8, 128/256-bit access,
// cache-hint matrix, block 128/256, persistent+prefetch, CE/SM split): none
// beat this; DRAM-active 82%, all compute pipes <6%.

#define QGRP (1 << 22)   // float4-granule count per t-stream (2^24 floats / 4)

__global__ void __launch_bounds__(256) gate_kernel(
    const float4* __restrict__ in4,
    const float*  __restrict__ m,
    float4*       __restrict__ out4)
{
    const int tid = blockIdx.x * blockDim.x + threadIdx.x;  // 0 .. 2^22-1

    float4 a0 = in4[tid];
    float4 a1 = in4[tid + QGRP];
    float4 a2 = in4[tid + 2 * QGRP];
    float4 a3 = in4[tid + 3 * QGRP];

    // control bit: bit 23 of element base (= tid*4) -> bit 21 of tid.
    // Uniform across 2^21 consecutive tids -> no warp divergence.
    if ((tid >> 21) & 1) {
        const float m00 = __ldg(m + 0),  m01 = __ldg(m + 1),  m02 = __ldg(m + 2),  m03 = __ldg(m + 3);
        const float m10 = __ldg(m + 4),  m11 = __ldg(m + 5),  m12 = __ldg(m + 6),  m13 = __ldg(m + 7);
        const float m20 = __ldg(m + 8),  m21 = __ldg(m + 9),  m22 = __ldg(m + 10), m23 = __ldg(m + 11);
        const float m30 = __ldg(m + 12), m31 = __ldg(m + 13), m32 = __ldg(m + 14), m33 = __ldg(m + 15);

        float4 y0, y1, y2, y3;
        #define APPLY(c) \
            y0.c = m00 * a0.c + m01 * a1.c + m02 * a2.c + m03 * a3.c; \
            y1.c = m10 * a0.c + m11 * a1.c + m12 * a2.c + m13 * a3.c; \
            y2.c = m20 * a0.c + m21 * a1.c + m22 * a2.c + m23 * a3.c; \
            y3.c = m30 * a0.c + m31 * a1.c + m32 * a2.c + m33 * a3.c;
        APPLY(x); APPLY(y); APPLY(z); APPLY(w);
        #undef APPLY

        a0 = y0; a1 = y1; a2 = y2; a3 = y3;
    }

    __stcs(out4 + tid,            a0);
    __stcs(out4 + tid + QGRP,     a1);
    __stcs(out4 + tid + 2 * QGRP, a2);
    __stcs(out4 + tid + 3 * QGRP, a3);
}

extern "C" void kernel_launch(void* const* d_in, const int* in_sizes, int n_in,
                              void* d_out, int out_size)
{
    const float* x = (const float*)d_in[0];   // 2^26 floats
    const float* m = (const float*)d_in[1];   // 16 floats (4x4 row-major)
    float* out = (float*)d_out;               // 2^26 floats

    const int n_threads = QGRP;               // 2^22 float4 groups
    const int block = 256;
    const int grid = n_threads / block;       // 16384
    gate_kernel<<<grid, block>>>((const float4*)x, m, (float4*)out);
}

// round 11
// speedup vs baseline: 1.0741x; 1.0008x over previous
#include <cuda_runtime.h>

// Controlled 2-qubit gate on a 2^26 fp32 statevector.
// Targets: qubits 0,1 -> bits 25,24 of the flat index. Control: qubit 2 -> bit 23.
// R4 structure (best, 74.4us): 1 float4 granule x 4 t-streams per thread,
// warp-uniform control branch, default-cache loads. Single change vs R4:
// WRITE-THROUGH stores (st.global.wt) instead of .cs — write data streams to
// DRAM continuously instead of draining in L2 dirty-eviction bursts, aiming
// at the read/write turnaround residue (DRAM-active 81.8% -> target ~84%).

#define QGRP (1 << 22)   // float4-granule count per t-stream (2^24 floats / 4)

__device__ __forceinline__ void stwt4(float4* p, float4 v) {
    asm volatile("st.global.wt.v4.f32 [%0], {%1,%2,%3,%4};"
                 :: "l"(p), "f"(v.x), "f"(v.y), "f"(v.z), "f"(v.w) : "memory");
}

__global__ void __launch_bounds__(256) gate_kernel(
    const float4* __restrict__ in4,
    const float*  __restrict__ m,
    float4*       __restrict__ out4)
{
    const int tid = blockIdx.x * blockDim.x + threadIdx.x;  // 0 .. 2^22-1

    float4 a0 = in4[tid];
    float4 a1 = in4[tid + QGRP];
    float4 a2 = in4[tid + 2 * QGRP];
    float4 a3 = in4[tid + 3 * QGRP];

    // control bit: bit 23 of element base (= tid*4) -> bit 21 of tid.
    // Uniform across 2^21 consecutive tids -> no warp divergence.
    if ((tid >> 21) & 1) {
        const float m00 = __ldg(m + 0),  m01 = __ldg(m + 1),  m02 = __ldg(m + 2),  m03 = __ldg(m + 3);
        const float m10 = __ldg(m + 4),  m11 = __ldg(m + 5),  m12 = __ldg(m + 6),  m13 = __ldg(m + 7);
        const float m20 = __ldg(m + 8),  m21 = __ldg(m + 9),  m22 = __ldg(m + 10), m23 = __ldg(m + 11);
        const float m30 = __ldg(m + 12), m31 = __ldg(m + 13), m32 = __ldg(m + 14), m33 = __ldg(m + 15);

        float4 y0, y1, y2, y3;
        #define APPLY(c) \
            y0.c = m00 * a0.c + m01 * a1.c + m02 * a2.c + m03 * a3.c; \
            y1.c = m10 * a0.c + m11 * a1.c + m12 * a2.c + m13 * a3.c; \
            y2.c = m20 * a0.c + m21 * a1.c + m22 * a2.c + m23 * a3.c; \
            y3.c = m30 * a0.c + m31 * a1.c + m32 * a2.c + m33 * a3.c;
        APPLY(x); APPLY(y); APPLY(z); APPLY(w);
        #undef APPLY

        a0 = y0; a1 = y1; a2 = y2; a3 = y3;
    }

    stwt4(out4 + tid,            a0);
    stwt4(out4 + tid + QGRP,     a1);
    stwt4(out4 + tid + 2 * QGRP, a2);
    stwt4(out4 + tid + 3 * QGRP, a3);
}

extern "C" void kernel_launch(void* const* d_in, const int* in_sizes, int n_in,
                              void* d_out, int out_size)
{
    const float* x = (const float*)d_in[0];   // 2^26 floats
    const float* m = (const float*)d_in[1];   // 16 floats (4x4 row-major)
    float* out = (float*)d_out;               // 2^26 floats

    const int n_threads = QGRP;               // 2^22 float4 groups
    const int block = 256;
    const int grid = n_threads / block;       // 16384
    gate_kernel<<<grid, block>>>((const float4*)x, m, (float4*)out);
}